// round 14
// baseline (speedup 1.0000x reference)
#include <cuda_runtime.h>
#include <cuda_bf16.h>
#include <cstdint>

// Problem constants
#define B_    8
#define C_    256
#define CI_   128
#define N_    3136
#define M_    1568
#define MPAD_ 1632            // 17*96
#define ROWS_ (B_*N_)         // 25088
#define KV    96

// ---------------- scratch (device globals; zero-initialized) --------------
__device__ __nv_bfloat16 d_th_hi[ROWS_*CI_];
__device__ __nv_bfloat16 d_th_lo[ROWS_*CI_];
__device__ __nv_bfloat16 d_ph_hi[B_*MPAD_*CI_];
__device__ __nv_bfloat16 d_ph_lo[B_*MPAD_*CI_];
__device__ __nv_bfloat16 d_g_hi [B_*MPAD_*CI_];
__device__ __nv_bfloat16 d_g_lo [B_*MPAD_*CI_];
// split-K attention partials
__device__ float d_py[2][ROWS_*CI_];
__device__ float d_pm[2][ROWS_];
__device__ float d_pl[2][ROWS_];

// ======================= helpers ==========================================
__device__ __forceinline__ uint32_t smem_u32(const void* p) {
    uint32_t a;
    asm("{ .reg .u64 t; cvta.to.shared.u64 t, %1; cvt.u32.u64 %0, t; }"
        : "=r"(a) : "l"(p));
    return a;
}
__device__ __forceinline__ void ldsm4(uint32_t r[4], uint32_t addr) {
    asm volatile("ldmatrix.sync.aligned.m8n8.x4.shared.b16 {%0,%1,%2,%3}, [%4];"
                 : "=r"(r[0]), "=r"(r[1]), "=r"(r[2]), "=r"(r[3]) : "r"(addr));
}
__device__ __forceinline__ void ldsm4t(uint32_t r[4], uint32_t addr) {
    asm volatile("ldmatrix.sync.aligned.m8n8.x4.trans.shared.b16 {%0,%1,%2,%3}, [%4];"
                 : "=r"(r[0]), "=r"(r[1]), "=r"(r[2]), "=r"(r[3]) : "r"(addr));
}
__device__ __forceinline__ void mma16816(float c[4],
                                         uint32_t a0, uint32_t a1, uint32_t a2, uint32_t a3,
                                         uint32_t b0, uint32_t b1) {
    asm volatile(
        "mma.sync.aligned.m16n8k16.row.col.f32.bf16.bf16.f32 "
        "{%0,%1,%2,%3}, {%4,%5,%6,%7}, {%8,%9}, {%0,%1,%2,%3};"
        : "+f"(c[0]), "+f"(c[1]), "+f"(c[2]), "+f"(c[3])
        : "r"(a0), "r"(a1), "r"(a2), "r"(a3), "r"(b0), "r"(b1));
}
__device__ __forceinline__ void cp16(uint32_t saddr, const void* gptr) {
    asm volatile("cp.async.cg.shared.global [%0], [%1], 16;"
                 :: "r"(saddr), "l"(gptr));
}
__device__ __forceinline__ uint32_t pack_bf16_hi(float x, float y) {
    __nv_bfloat16 hx = __float2bfloat16(x), hy = __float2bfloat16(y);
    return (uint32_t)__bfloat16_as_ushort(hx) |
           ((uint32_t)__bfloat16_as_ushort(hy) << 16);
}
__device__ __forceinline__ uint32_t pack_bf16_lo(float x, float y) {
    __nv_bfloat16 hx = __float2bfloat16(x), hy = __float2bfloat16(y);
    __nv_bfloat16 lx = __float2bfloat16(x - __bfloat162float(hx));
    __nv_bfloat16 ly = __float2bfloat16(y - __bfloat162float(hy));
    return (uint32_t)__bfloat16_as_ushort(lx) |
           ((uint32_t)__bfloat16_as_ushort(ly) << 16);
}

// SMEM strides
#define SB_      272
#define SBB_     144
// attention smem: 2 buffers of [ph_hi|ph_lo|g_hi|g_lo], each 96 rows
#define A_PHH    0
#define A_PHL    26112
#define A_GH     52224
#define A_GL     78336
#define BUFA     104448
#define SM_ATTN  (2*BUFA)                // 208896
// gemm (proj col-split) smem
#define OFF_AH   0
#define OFF_AL   34816
#define OFF_BH   69632
#define OFF_BL   (69632 + 18432)
#define SM_PROJ  (OFF_BL + 18432)        // 106496 -> 2 CTAs/SM
// final (128-wide) smem
#define F_AH     0
#define F_AL     34816
#define F_BH     69632
#define F_BL     104448
#define SM_FIN   139264

// ===========================================================================
// K1: projections, col-split 64-wide; mma pairs interleaved (RAW dist 4)
// ===========================================================================
__global__ __launch_bounds__(256, 2)
void k_projmma(const float* __restrict__ X,
               const float* __restrict__ Wt,
               const float* __restrict__ Wp,
               const float* __restrict__ Wg)
{
    extern __shared__ char smem[];
    const uint32_t sb = smem_u32(smem);
    const int wi = blockIdx.y;
    const int ch = blockIdx.z;
    const float* Wsel = (wi == 0) ? Wt : ((wi == 1) ? Wp : Wg);
    const int r0 = blockIdx.x * 128;
    const int t  = threadIdx.x;
    const int w  = t >> 5;
    const int lane = t & 31;
    const int tg  = lane >> 3;
    const int tr8 = lane & 7;
    const int aA_row  = ((tg & 1) << 3) + tr8;
    const int aA_colb = (tg & 2) * 8;

    const uint32_t ahA = sb + OFF_AH + (uint32_t)(16 * w + aA_row) * SB_ + aA_colb;
    const uint32_t alA = sb + OFF_AL + (uint32_t)(16 * w + aA_row) * SB_ + aA_colb;
    const uint32_t bhB = sb + OFF_BH + (uint32_t)aA_row * SBB_ + aA_colb;
    const uint32_t blB = sb + OFF_BL + (uint32_t)aA_row * SBB_ + aA_colb;

    float yv[8][4];
#pragma unroll
    for (int f = 0; f < 8; f++)
#pragma unroll
        for (int j = 0; j < 4; j++) yv[f][j] = 0.f;

    for (int kc = 0; kc < 2; kc++) {
        if (kc) __syncthreads();
#pragma unroll
        for (int q = 0; q < 16; q++) {
            int i = t + 256 * q;
            int r = i >> 5, c4 = (i & 31) * 4;
            float4 v = *(const float4*)&X[(size_t)(r0 + r) * 256 + kc * 128 + c4];
            uint2 h = { pack_bf16_hi(v.x, v.y), pack_bf16_hi(v.z, v.w) };
            uint2 l = { pack_bf16_lo(v.x, v.y), pack_bf16_lo(v.z, v.w) };
            *(uint2*)(smem + OFF_AH + r * SB_ + c4 * 2) = h;
            *(uint2*)(smem + OFF_AL + r * SB_ + c4 * 2) = l;
        }
#pragma unroll
        for (int q = 0; q < 8; q++) {
            int i = t + 256 * q;
            int r = i >> 4, c4 = (i & 15) * 4;
            float4 wv = *(const float4*)&Wsel[(size_t)(kc * 128 + r) * 128 + ch * 64 + c4];
            uint2 wh = { pack_bf16_hi(wv.x, wv.y), pack_bf16_hi(wv.z, wv.w) };
            uint2 wl = { pack_bf16_lo(wv.x, wv.y), pack_bf16_lo(wv.z, wv.w) };
            *(uint2*)(smem + OFF_BH + r * SBB_ + c4 * 2) = wh;
            *(uint2*)(smem + OFF_BL + r * SBB_ + c4 * 2) = wl;
        }
        __syncthreads();

#pragma unroll
        for (int k = 0; k < 8; k++) {
            uint32_t ah[4], al[4];
            ldsm4(ah, ahA + k * 32);
            ldsm4(al, alA + k * 32);
#pragma unroll
            for (int gp = 0; gp < 2; gp++) {
                const int a = 2 * gp, bq = 2 * gp + 1;
                uint32_t ba[4], bb[4];
                ldsm4t(ba, bhB + (uint32_t)(k * 16) * SBB_ + a * 32);
                ldsm4t(bb, bhB + (uint32_t)(k * 16) * SBB_ + bq * 32);
                mma16816(yv[2*a],    ah[0], ah[1], ah[2], ah[3], ba[0], ba[1]);
                mma16816(yv[2*a+1],  ah[0], ah[1], ah[2], ah[3], ba[2], ba[3]);
                mma16816(yv[2*bq],   ah[0], ah[1], ah[2], ah[3], bb[0], bb[1]);
                mma16816(yv[2*bq+1], ah[0], ah[1], ah[2], ah[3], bb[2], bb[3]);
                mma16816(yv[2*a],    al[0], al[1], al[2], al[3], ba[0], ba[1]);
                mma16816(yv[2*a+1],  al[0], al[1], al[2], al[3], ba[2], ba[3]);
                mma16816(yv[2*bq],   al[0], al[1], al[2], al[3], bb[0], bb[1]);
                mma16816(yv[2*bq+1], al[0], al[1], al[2], al[3], bb[2], bb[3]);
            }
#pragma unroll
            for (int gp = 0; gp < 2; gp++) {
                const int a = 2 * gp, bq = 2 * gp + 1;
                uint32_t ba[4], bb[4];
                ldsm4t(ba, blB + (uint32_t)(k * 16) * SBB_ + a * 32);
                ldsm4t(bb, blB + (uint32_t)(k * 16) * SBB_ + bq * 32);
                mma16816(yv[2*a],    ah[0], ah[1], ah[2], ah[3], ba[0], ba[1]);
                mma16816(yv[2*a+1],  ah[0], ah[1], ah[2], ah[3], ba[2], ba[3]);
                mma16816(yv[2*bq],   ah[0], ah[1], ah[2], ah[3], bb[0], bb[1]);
                mma16816(yv[2*bq+1], ah[0], ah[1], ah[2], ah[3], bb[2], bb[3]);
            }
        }
    }

    const int q  = lane >> 2;
    const int cb = 2 * (lane & 3);
    if (wi == 0) {
        const size_t rA = (size_t)(r0 + 16 * w + q) * 128 + ch * 64;
        const size_t rB = rA + 8 * 128;
#pragma unroll
        for (int nf = 0; nf < 8; nf++) {
            int c = nf * 8 + cb;
            *(uint32_t*)&d_th_hi[rA + c] = pack_bf16_hi(yv[nf][0], yv[nf][1]);
            *(uint32_t*)&d_th_lo[rA + c] = pack_bf16_lo(yv[nf][0], yv[nf][1]);
            *(uint32_t*)&d_th_hi[rB + c] = pack_bf16_hi(yv[nf][2], yv[nf][3]);
            *(uint32_t*)&d_th_lo[rB + c] = pack_bf16_lo(yv[nf][2], yv[nf][3]);
        }
    } else {
        __nv_bfloat16* dh = (wi == 1) ? d_ph_hi : d_g_hi;
        __nv_bfloat16* dl = (wi == 1) ? d_ph_lo : d_g_lo;
        float pm[8][4];
#pragma unroll
        for (int nf = 0; nf < 8; nf++)
#pragma unroll
            for (int j = 0; j < 4; j++)
                pm[nf][j] = fmaxf(yv[nf][j],
                                  __shfl_xor_sync(0xffffffffu, yv[nf][j], 4));
        if ((q & 1) == 0) {
            int rpA = (r0 + 16 * w + q) >> 1;
            int rpB = (r0 + 16 * w + 8 + q) >> 1;
            int bA = rpA / M_, mA = rpA - bA * M_;
            int bB = rpB / M_, mB = rpB - bB * M_;
            size_t dA = ((size_t)bA * MPAD_ + mA) * 128 + ch * 64;
            size_t dB = ((size_t)bB * MPAD_ + mB) * 128 + ch * 64;
#pragma unroll
            for (int nf = 0; nf < 8; nf++) {
                int c = nf * 8 + cb;
                *(uint32_t*)&dh[dA + c] = pack_bf16_hi(pm[nf][0], pm[nf][1]);
                *(uint32_t*)&dl[dA + c] = pack_bf16_lo(pm[nf][0], pm[nf][1]);
                *(uint32_t*)&dh[dB + c] = pack_bf16_hi(pm[nf][2], pm[nf][3]);
                *(uint32_t*)&dl[dB + c] = pack_bf16_lo(pm[nf][2], pm[nf][3]);
            }
        }
    }
}

// ===========================================================================
// K3: split-K flash attention (R13 winner, unchanged)
// ===========================================================================
__global__ __launch_bounds__(256, 1)
void k_attn14()
{
    extern __shared__ char smem[];
    const uint32_t sb = smem_u32(smem);
    const int b    = blockIdx.y;
    const int half = blockIdx.z;
    const int n0   = blockIdx.x * 128;
    const int t  = threadIdx.x;
    const int w  = t >> 5;
    const int lane = t & 31;
    const int tg  = lane >> 3;
    const int tr8 = lane & 7;

    const int aA_row  = ((tg & 1) << 3) + tr8;
    const int aA_colb = (tg & 2) * 8;
    const int bp_row  = ((tg & 2) << 2) + tr8;
    const int bp_colb = (tg & 1) * 16;

    const uint32_t phB_r = (uint32_t)bp_row * SB_ + bp_colb;
    const uint32_t ghB_r = (uint32_t)aA_row * SB_ + aA_colb;

    const int it0 = (half == 0) ? 0 : 9;
    const int nIt = (half == 0) ? 9 : 8;

    const int ld_r  = t >> 4;
    const int ld_c8 = (t & 15) * 8;

    uint32_t ath[8][4], atl[8][4];
    {
        int r0q = n0 + 16 * w + (lane >> 2);
        int rA = (r0q     < N_) ? r0q     : (N_ - 1);
        int rB = (r0q + 8 < N_) ? r0q + 8 : (N_ - 1);
        const __nv_bfloat16* th = d_th_hi + (size_t)b * N_ * 128;
        const __nv_bfloat16* tl = d_th_lo + (size_t)b * N_ * 128;
        const int cbf = (lane & 3) * 2;
#pragma unroll
        for (int k = 0; k < 8; k++) {
            int c = k * 16 + cbf;
            ath[k][0] = *(const uint32_t*)(th + (size_t)rA * 128 + c);
            ath[k][1] = *(const uint32_t*)(th + (size_t)rB * 128 + c);
            ath[k][2] = *(const uint32_t*)(th + (size_t)rA * 128 + c + 8);
            ath[k][3] = *(const uint32_t*)(th + (size_t)rB * 128 + c + 8);
            atl[k][0] = *(const uint32_t*)(tl + (size_t)rA * 128 + c);
            atl[k][1] = *(const uint32_t*)(tl + (size_t)rB * 128 + c);
            atl[k][2] = *(const uint32_t*)(tl + (size_t)rA * 128 + c + 8);
            atl[k][3] = *(const uint32_t*)(tl + (size_t)rB * 128 + c + 8);
        }
    }

    {
        const int m0 = it0 * KV;
#pragma unroll
        for (int q = 0; q < 6; q++) {
            int r = ld_r + 16 * q;
            size_t gidx = ((size_t)b * MPAD_ + m0 + r) * 128 + ld_c8;
            uint32_t so = sb + (uint32_t)r * SB_ + ld_c8 * 2;
            cp16(so + A_PHH, d_ph_hi + gidx);
            cp16(so + A_PHL, d_ph_lo + gidx);
            cp16(so + A_GH,  d_g_hi  + gidx);
            cp16(so + A_GL,  d_g_lo  + gidx);
        }
        asm volatile("cp.async.commit_group;");
    }

    float yv[16][4];
#pragma unroll
    for (int f = 0; f < 16; f++)
#pragma unroll
        for (int j = 0; j < 4; j++) yv[f][j] = 0.f;
    float mA = 0.f, mB = 0.f, lA = 0.f, lB = 0.f;

    for (int ii = 0; ii < nIt; ii++) {
        if (ii + 1 < nIt) {
            const int m0n = (it0 + ii + 1) * KV;
            const uint32_t bufn = sb + (uint32_t)((ii + 1) & 1) * BUFA;
#pragma unroll
            for (int q = 0; q < 6; q++) {
                int r = ld_r + 16 * q;
                size_t gidx = ((size_t)b * MPAD_ + m0n + r) * 128 + ld_c8;
                uint32_t so = bufn + (uint32_t)r * SB_ + ld_c8 * 2;
                cp16(so + A_PHH, d_ph_hi + gidx);
                cp16(so + A_PHL, d_ph_lo + gidx);
                cp16(so + A_GH,  d_g_hi  + gidx);
                cp16(so + A_GL,  d_g_lo  + gidx);
            }
            asm volatile("cp.async.commit_group;");
            asm volatile("cp.async.wait_group 1;");
        } else {
            asm volatile("cp.async.wait_group 0;");
        }
        __syncthreads();

        const uint32_t bufc = sb + (uint32_t)(ii & 1) * BUFA;
        const uint32_t phB = bufc + A_PHH + phB_r;
        const uint32_t plB = bufc + A_PHL + phB_r;
        const uint32_t ghB = bufc + A_GH  + ghB_r;
        const uint32_t glB = bufc + A_GL  + ghB_r;

        float sf[12][4];
#pragma unroll
        for (int f = 0; f < 12; f++)
#pragma unroll
            for (int j = 0; j < 4; j++) sf[f][j] = 0.f;

#pragma unroll
        for (int k = 0; k < 8; k++) {
#pragma unroll
            for (int np = 0; np < 3; np++) {
                const int a = 2 * np, bq = 2 * np + 1;
                uint32_t ba[4], bb[4];
                ldsm4(ba, phB + (uint32_t)(a  * 16) * SB_ + k * 32);
                ldsm4(bb, phB + (uint32_t)(bq * 16) * SB_ + k * 32);
                mma16816(sf[2*a],    ath[k][0], ath[k][1], ath[k][2], ath[k][3], ba[0], ba[1]);
                mma16816(sf[2*a+1],  ath[k][0], ath[k][1], ath[k][2], ath[k][3], ba[2], ba[3]);
                mma16816(sf[2*bq],   ath[k][0], ath[k][1], ath[k][2], ath[k][3], bb[0], bb[1]);
                mma16816(sf[2*bq+1], ath[k][0], ath[k][1], ath[k][2], ath[k][3], bb[2], bb[3]);
                mma16816(sf[2*a],    atl[k][0], atl[k][1], atl[k][2], atl[k][3], ba[0], ba[1]);
                mma16816(sf[2*a+1],  atl[k][0], atl[k][1], atl[k][2], atl[k][3], ba[2], ba[3]);
                mma16816(sf[2*bq],   atl[k][0], atl[k][1], atl[k][2], atl[k][3], bb[0], bb[1]);
                mma16816(sf[2*bq+1], atl[k][0], atl[k][1], atl[k][2], atl[k][3], bb[2], bb[3]);
            }
#pragma unroll
            for (int np = 0; np < 3; np++) {
                const int a = 2 * np, bq = 2 * np + 1;
                uint32_t ba[4], bb[4];
                ldsm4(ba, plB + (uint32_t)(a  * 16) * SB_ + k * 32);
                ldsm4(bb, plB + (uint32_t)(bq * 16) * SB_ + k * 32);
                mma16816(sf[2*a],    ath[k][0], ath[k][1], ath[k][2], ath[k][3], ba[0], ba[1]);
                mma16816(sf[2*a+1],  ath[k][0], ath[k][1], ath[k][2], ath[k][3], ba[2], ba[3]);
                mma16816(sf[2*bq],   ath[k][0], ath[k][1], ath[k][2], ath[k][3], bb[0], bb[1]);
                mma16816(sf[2*bq+1], ath[k][0], ath[k][1], ath[k][2], ath[k][3], bb[2], bb[3]);
            }
        }

        if (ii == 0) {
            float mxA = -1e30f, mxB = -1e30f;
#pragma unroll
            for (int f = 0; f < 12; f++) {
                mxA = fmaxf(mxA, fmaxf(sf[f][0], sf[f][1]));
                mxB = fmaxf(mxB, fmaxf(sf[f][2], sf[f][3]));
            }
            mxA = fmaxf(mxA, __shfl_xor_sync(0xffffffffu, mxA, 1));
            mxA = fmaxf(mxA, __shfl_xor_sync(0xffffffffu, mxA, 2));
            mxB = fmaxf(mxB, __shfl_xor_sync(0xffffffffu, mxB, 1));
            mxB = fmaxf(mxB, __shfl_xor_sync(0xffffffffu, mxB, 2));
            mA = mxA; mB = mxB;
        }

#pragma unroll
        for (int ks = 0; ks < 6; ks++) {
            uint32_t pah[4], pal[4];
#pragma unroll
            for (int h = 0; h < 2; h++) {
                int f = 2 * ks + h;
                float p0 = __expf(sf[f][0] - mA);
                float p1 = __expf(sf[f][1] - mA);
                float p2 = __expf(sf[f][2] - mB);
                float p3 = __expf(sf[f][3] - mB);
                lA += p0 + p1; lB += p2 + p3;
                pah[0 + 2 * h] = pack_bf16_hi(p0, p1);
                pah[1 + 2 * h] = pack_bf16_hi(p2, p3);
                pal[0 + 2 * h] = pack_bf16_lo(p0, p1);
                pal[1 + 2 * h] = pack_bf16_lo(p2, p3);
            }
            const uint32_t gb = (uint32_t)(ks * 16) * SB_;
#pragma unroll
            for (int gp = 0; gp < 4; gp++) {
                const int a = 2 * gp, bq = 2 * gp + 1;
                uint32_t ba[4], bb[4];
                ldsm4t(ba, ghB + gb + a  * 32);
                ldsm4t(bb, ghB + gb + bq * 32);
                mma16816(yv[2*a],    pah[0], pah[1], pah[2], pah[3], ba[0], ba[1]);
                mma16816(yv[2*a+1],  pah[0], pah[1], pah[2], pah[3], ba[2], ba[3]);
                mma16816(yv[2*bq],   pah[0], pah[1], pah[2], pah[3], bb[0], bb[1]);
                mma16816(yv[2*bq+1], pah[0], pah[1], pah[2], pah[3], bb[2], bb[3]);
                mma16816(yv[2*a],    pal[0], pal[1], pal[2], pal[3], ba[0], ba[1]);
                mma16816(yv[2*a+1],  pal[0], pal[1], pal[2], pal[3], ba[2], ba[3]);
                mma16816(yv[2*bq],   pal[0], pal[1], pal[2], pal[3], bb[0], bb[1]);
                mma16816(yv[2*bq+1], pal[0], pal[1], pal[2], pal[3], bb[2], bb[3]);
            }
#pragma unroll
            for (int gp = 0; gp < 4; gp++) {
                const int a = 2 * gp, bq = 2 * gp + 1;
                uint32_t ba[4], bb[4];
                ldsm4t(ba, glB + gb + a  * 32);
                ldsm4t(bb, glB + gb + bq * 32);
                mma16816(yv[2*a],    pah[0], pah[1], pah[2], pah[3], ba[0], ba[1]);
                mma16816(yv[2*a+1],  pah[0], pah[1], pah[2], pah[3], ba[2], ba[3]);
                mma16816(yv[2*bq],   pah[0], pah[1], pah[2], pah[3], bb[0], bb[1]);
                mma16816(yv[2*bq+1], pah[0], pah[1], pah[2], pah[3], bb[2], bb[3]);
            }
        }
        __syncthreads();
    }

    lA += __shfl_xor_sync(0xffffffffu, lA, 1);
    lA += __shfl_xor_sync(0xffffffffu, lA, 2);
    lB += __shfl_xor_sync(0xffffffffu, lB, 1);
    lB += __shfl_xor_sync(0xffffffffu, lB, 2);

    const int nA = n0 + 16 * w + (lane >> 2);
    const int nB = nA + 8;
    const int cb = 2 * (lane & 3);
    if (nA < N_) {
        size_t base = ((size_t)b * N_ + nA) * 128;
#pragma unroll
        for (int nf = 0; nf < 16; nf++) {
            float2 v = { yv[nf][0], yv[nf][1] };
            *(float2*)&d_py[half][base + nf * 8 + cb] = v;
        }
        if ((lane & 3) == 0) {
            d_pm[half][b * N_ + nA] = mA;
            d_pl[half][b * N_ + nA] = lA;
        }
    }
    if (nB < N_) {
        size_t base = ((size_t)b * N_ + nB) * 128;
#pragma unroll
        for (int nf = 0; nf < 16; nf++) {
            float2 v = { yv[nf][2], yv[nf][3] };
            *(float2*)&d_py[half][base + nf * 8 + cb] = v;
        }
        if ((lane & 3) == 0) {
            d_pm[half][b * N_ + nB] = mB;
            d_pl[half][b * N_ + nB] = lB;
        }
    }
}

// ===========================================================================
// K4: out = x + Y @ Wf (128-wide) with FUSED split-K combine in the A-stage.
// ===========================================================================
__global__ __launch_bounds__(256, 1)
void k_finalmma(const float* __restrict__ X,
                const float* __restrict__ Wf,
                float* __restrict__ out)
{
    extern __shared__ char smem[];
    const uint32_t sb = smem_u32(smem);
    const int r0 = blockIdx.x * 128;
    const int ch = blockIdx.y;
    const int t  = threadIdx.x;
    const int w  = t >> 5;
    const int lane = t & 31;
    const int tg  = lane >> 3;
    const int tr8 = lane & 7;
    const int aA_row  = ((tg & 1) << 3) + tr8;
    const int aA_colb = (tg & 2) * 8;

    const uint32_t ahA = sb + F_AH + (uint32_t)(16 * w + aA_row) * SB_ + aA_colb;
    const uint32_t alA = sb + F_AL + (uint32_t)(16 * w + aA_row) * SB_ + aA_colb;
    const uint32_t bhB = sb + F_BH + (uint32_t)aA_row * SB_ + aA_colb;
    const uint32_t blB = sb + F_BL + (uint32_t)aA_row * SB_ + aA_colb;

    // ---- A: fused combine of split-K partials -> split-bf16 smem tile ----
#pragma unroll
    for (int qq = 0; qq < 8; qq++) {
        int i = t + 256 * qq;
        int r = i >> 4, c8 = (i & 15) * 8;
        int row = r0 + r;
        float m0 = d_pm[0][row], m1 = d_pm[1][row];
        float l0 = d_pl[0][row], l1 = d_pl[1][row];
        float m  = fmaxf(m0, m1);
        float w0 = __expf(m0 - m), w1 = __expf(m1 - m);
        float inv = 1.f / (l0 * w0 + l1 * w1);
        w0 *= inv; w1 *= inv;
        size_t base = (size_t)row * 128 + c8;
        float4 a0 = *(const float4*)&d_py[0][base];
        float4 a1 = *(const float4*)&d_py[1][base];
        float4 b0 = *(const float4*)&d_py[0][base + 4];
        float4 b1 = *(const float4*)&d_py[1][base + 4];
        float v0 = a0.x * w0 + a1.x * w1;
        float v1 = a0.y * w0 + a1.y * w1;
        float v2 = a0.z * w0 + a1.z * w1;
        float v3 = a0.w * w0 + a1.w * w1;
        float v4 = b0.x * w0 + b1.x * w1;
        float v5 = b0.y * w0 + b1.y * w1;
        float v6 = b0.z * w0 + b1.z * w1;
        float v7 = b0.w * w0 + b1.w * w1;
        uint4 hh = { pack_bf16_hi(v0, v1), pack_bf16_hi(v2, v3),
                     pack_bf16_hi(v4, v5), pack_bf16_hi(v6, v7) };
        uint4 ll = { pack_bf16_lo(v0, v1), pack_bf16_lo(v2, v3),
                     pack_bf16_lo(v4, v5), pack_bf16_lo(v6, v7) };
        *(uint4*)(smem + F_AH + r * SB_ + c8 * 2) = hh;
        *(uint4*)(smem + F_AL + r * SB_ + c8 * 2) = ll;
    }
    // ---- B: Wf split-load ----
#pragma unroll
    for (int q = 0; q < 16; q++) {
        int i = t + 256 * q;
        int r = i >> 5, c4 = (i & 31) * 4;
        float4 wv = *(const float4*)&Wf[(size_t)r * 256 + ch * 128 + c4];
        uint2 wh = { pack_bf16_hi(wv.x, wv.y), pack_bf16_hi(wv.z, wv.w) };
        uint2 wl = { pack_bf16_lo(wv.x, wv.y), pack_bf16_lo(wv.z, wv.w) };
        *(uint2*)(smem + F_BH + r * SB_ + c4 * 2) = wh;
        *(uint2*)(smem + F_BL + r * SB_ + c4 * 2) = wl;
    }
    __syncthreads();

    float yv[16][4];
#pragma unroll
    for (int f = 0; f < 16; f++)
#pragma unroll
        for (int j = 0; j < 4; j++) yv[f][j] = 0.f;

#pragma unroll
    for (int k = 0; k < 8; k++) {
        uint32_t ah[4], al[4];
        ldsm4(ah, ahA + k * 32);
        ldsm4(al, alA + k * 32);
#pragma unroll
        for (int gp = 0; gp < 4; gp++) {
            const int a = 2 * gp, bq = 2 * gp + 1;
            uint32_t ba[4], bb[4];
            ldsm4t(ba, bhB + (uint32_t)(k * 16) * SB_ + a  * 32);
            ldsm4t(bb, bhB + (uint32_t)(k * 16) * SB_ + bq * 32);
            mma16816(yv[2*a],    ah[0], ah[1], ah[2], ah[3], ba[0], ba[1]);
            mma16816(yv[2*a+1],  ah[0], ah[1], ah[2], ah[3], ba[2], ba[3]);
            mma16816(yv[2*bq],   ah[0], ah[1], ah[2], ah[3], bb[0], bb[1]);
            mma16816(yv[2*bq+1], ah[0], ah[1], ah[2], ah[3], bb[2], bb[3]);
            mma16816(yv[2*a],    al[0], al[1], al[2], al[3], ba[0], ba[1]);
            mma16816(yv[2*a+1],  al[0], al[1], al[2], al[3], ba[2], ba[3]);
            mma16816(yv[2*bq],   al[0], al[1], al[2], al[3], bb[0], bb[1]);
            mma16816(yv[2*bq+1], al[0], al[1], al[2], al[3], bb[2], bb[3]);
        }
#pragma unroll
        for (int gp = 0; gp < 4; gp++) {
            const int a = 2 * gp, bq = 2 * gp + 1;
            uint32_t ba[4], bb[4];
            ldsm4t(ba, blB + (uint32_t)(k * 16) * SB_ + a  * 32);
            ldsm4t(bb, blB + (uint32_t)(k * 16) * SB_ + bq * 32);
            mma16816(yv[2*a],    ah[0], ah[1], ah[2], ah[3], ba[0], ba[1]);
            mma16816(yv[2*a+1],  ah[0], ah[1], ah[2], ah[3], ba[2], ba[3]);
            mma16816(yv[2*bq],   ah[0], ah[1], ah[2], ah[3], bb[0], bb[1]);
            mma16816(yv[2*bq+1], ah[0], ah[1], ah[2], ah[3], bb[2], bb[3]);
        }
    }

    const int q  = lane >> 2;
    const int cb = 2 * (lane & 3);
    const size_t rA = (size_t)(r0 + 16 * w + q) * 256 + ch * 128;
    const size_t rB = rA + 8 * 256;
#pragma unroll
    for (int nf = 0; nf < 16; nf++) {
        int c = nf * 8 + cb;
        float2 xa = *(const float2*)&X[rA + c];
        float2 xb = *(const float2*)&X[rB + c];
        float2 oa = { xa.x + yv[nf][0], xa.y + yv[nf][1] };
        float2 ob = { xb.x + yv[nf][2], xb.y + yv[nf][3] };
        *(float2*)&out[rA + c] = oa;
        *(float2*)&out[rB + c] = ob;
    }
}

// ===========================================================================
extern "C" void kernel_launch(void* const* d_in, const int* in_sizes, int n_in,
                              void* d_out, int out_size)
{
    const float* x  = (const float*)d_in[0];
    const float* wt = (const float*)d_in[1];
    const float* wp = (const float*)d_in[2];
    const float* wg = (const float*)d_in[3];
    const float* wf = (const float*)d_in[4];
    float* out = (float*)d_out;

    cudaFuncSetAttribute(k_projmma,  cudaFuncAttributeMaxDynamicSharedMemorySize, SM_PROJ);
    cudaFuncSetAttribute(k_attn14,   cudaFuncAttributeMaxDynamicSharedMemorySize, SM_ATTN);
    cudaFuncSetAttribute(k_finalmma, cudaFuncAttributeMaxDynamicSharedMemorySize, SM_FIN);

    {
        dim3 grid(ROWS_ / 128, 3, 2);
        k_projmma<<<grid, 256, SM_PROJ>>>(x, wt, wp, wg);
    }
    {
        dim3 grid(25, B_, 2);
        k_attn14<<<grid, 256, SM_ATTN>>>();
    }
    {
        dim3 grid(ROWS_ / 128, 2);
        k_finalmma<<<grid, 256, SM_FIN>>>(x, wf, out);
    }
}

// round 15
// speedup vs baseline: 1.0192x; 1.0192x over previous
#include <cuda_runtime.h>
#include <cuda_bf16.h>
#include <cstdint>

// Problem constants
#define B_    8
#define C_    256
#define CI_   128
#define N_    3136
#define M_    1568
#define MPAD_ 1632            // 17*96
#define ROWS_ (B_*N_)         // 25088
#define KV    96

// ---------------- scratch (device globals; zero-initialized) --------------
__device__ __nv_bfloat16 d_th_hi[ROWS_*CI_];
__device__ __nv_bfloat16 d_th_lo[ROWS_*CI_];
__device__ __nv_bfloat16 d_ph_hi[B_*MPAD_*CI_];
__device__ __nv_bfloat16 d_ph_lo[B_*MPAD_*CI_];
__device__ __nv_bfloat16 d_g_hi [B_*MPAD_*CI_];
__device__ __nv_bfloat16 d_g_lo [B_*MPAD_*CI_];
__device__ __nv_bfloat16 d_y_hi [ROWS_*CI_];
__device__ __nv_bfloat16 d_y_lo [ROWS_*CI_];
// split-K attention partials
__device__ float d_py[2][ROWS_*CI_];
__device__ float d_pm[2][ROWS_];
__device__ float d_pl[2][ROWS_];

// ======================= helpers ==========================================
__device__ __forceinline__ uint32_t smem_u32(const void* p) {
    uint32_t a;
    asm("{ .reg .u64 t; cvta.to.shared.u64 t, %1; cvt.u32.u64 %0, t; }"
        : "=r"(a) : "l"(p));
    return a;
}
__device__ __forceinline__ void ldsm4(uint32_t r[4], uint32_t addr) {
    asm volatile("ldmatrix.sync.aligned.m8n8.x4.shared.b16 {%0,%1,%2,%3}, [%4];"
                 : "=r"(r[0]), "=r"(r[1]), "=r"(r[2]), "=r"(r[3]) : "r"(addr));
}
__device__ __forceinline__ void ldsm4t(uint32_t r[4], uint32_t addr) {
    asm volatile("ldmatrix.sync.aligned.m8n8.x4.trans.shared.b16 {%0,%1,%2,%3}, [%4];"
                 : "=r"(r[0]), "=r"(r[1]), "=r"(r[2]), "=r"(r[3]) : "r"(addr));
}
__device__ __forceinline__ void mma16816(float c[4],
                                         uint32_t a0, uint32_t a1, uint32_t a2, uint32_t a3,
                                         uint32_t b0, uint32_t b1) {
    asm volatile(
        "mma.sync.aligned.m16n8k16.row.col.f32.bf16.bf16.f32 "
        "{%0,%1,%2,%3}, {%4,%5,%6,%7}, {%8,%9}, {%0,%1,%2,%3};"
        : "+f"(c[0]), "+f"(c[1]), "+f"(c[2]), "+f"(c[3])
        : "r"(a0), "r"(a1), "r"(a2), "r"(a3), "r"(b0), "r"(b1));
}
__device__ __forceinline__ void cp16(uint32_t saddr, const void* gptr) {
    asm volatile("cp.async.cg.shared.global [%0], [%1], 16;"
                 :: "r"(saddr), "l"(gptr));
}
__device__ __forceinline__ uint32_t pack_bf16_hi(float x, float y) {
    __nv_bfloat16 hx = __float2bfloat16(x), hy = __float2bfloat16(y);
    return (uint32_t)__bfloat16_as_ushort(hx) |
           ((uint32_t)__bfloat16_as_ushort(hy) << 16);
}
__device__ __forceinline__ uint32_t pack_bf16_lo(float x, float y) {
    __nv_bfloat16 hx = __float2bfloat16(x), hy = __float2bfloat16(y);
    __nv_bfloat16 lx = __float2bfloat16(x - __bfloat162float(hx));
    __nv_bfloat16 ly = __float2bfloat16(y - __bfloat162float(hy));
    return (uint32_t)__bfloat16_as_ushort(lx) |
           ((uint32_t)__bfloat16_as_ushort(ly) << 16);
}

// SMEM strides
#define SB_      272
#define SBB_     144
// attention smem: 2 buffers of [ph_hi|ph_lo|g_hi|g_lo], each 96 rows
#define A_PHH    0
#define A_PHL    26112
#define A_GH     52224
#define A_GL     78336
#define BUFA     104448
#define SM_ATTN  (2*BUFA)                // 208896
// gemm (proj col-split) smem
#define OFF_AH   0
#define OFF_AL   34816
#define OFF_BH   69632
#define OFF_BL   (69632 + 18432)
#define SM_PROJ  (OFF_BL + 18432)        // 106496 -> 2 CTAs/SM
// final (128-wide) smem
#define F_AH     0
#define F_AL     34816
#define F_BH     69632
#define F_BL     104448
#define SM_FIN   139264

// ===========================================================================
// K1: projections, col-split 64-wide; mma pairs interleaved (R13)
// ===========================================================================
__global__ __launch_bounds__(256, 2)
void k_projmma(const float* __restrict__ X,
               const float* __restrict__ Wt,
               const float* __restrict__ Wp,
               const float* __restrict__ Wg)
{
    extern __shared__ char smem[];
    const uint32_t sb = smem_u32(smem);
    const int wi = blockIdx.y;
    const int ch = blockIdx.z;
    const float* Wsel = (wi == 0) ? Wt : ((wi == 1) ? Wp : Wg);
    const int r0 = blockIdx.x * 128;
    const int t  = threadIdx.x;
    const int w  = t >> 5;
    const int lane = t & 31;
    const int tg  = lane >> 3;
    const int tr8 = lane & 7;
    const int aA_row  = ((tg & 1) << 3) + tr8;
    const int aA_colb = (tg & 2) * 8;

    const uint32_t ahA = sb + OFF_AH + (uint32_t)(16 * w + aA_row) * SB_ + aA_colb;
    const uint32_t alA = sb + OFF_AL + (uint32_t)(16 * w + aA_row) * SB_ + aA_colb;
    const uint32_t bhB = sb + OFF_BH + (uint32_t)aA_row * SBB_ + aA_colb;
    const uint32_t blB = sb + OFF_BL + (uint32_t)aA_row * SBB_ + aA_colb;

    float yv[8][4];
#pragma unroll
    for (int f = 0; f < 8; f++)
#pragma unroll
        for (int j = 0; j < 4; j++) yv[f][j] = 0.f;

    for (int kc = 0; kc < 2; kc++) {
        if (kc) __syncthreads();
#pragma unroll
        for (int q = 0; q < 16; q++) {
            int i = t + 256 * q;
            int r = i >> 5, c4 = (i & 31) * 4;
            float4 v = *(const float4*)&X[(size_t)(r0 + r) * 256 + kc * 128 + c4];
            uint2 h = { pack_bf16_hi(v.x, v.y), pack_bf16_hi(v.z, v.w) };
            uint2 l = { pack_bf16_lo(v.x, v.y), pack_bf16_lo(v.z, v.w) };
            *(uint2*)(smem + OFF_AH + r * SB_ + c4 * 2) = h;
            *(uint2*)(smem + OFF_AL + r * SB_ + c4 * 2) = l;
        }
#pragma unroll
        for (int q = 0; q < 8; q++) {
            int i = t + 256 * q;
            int r = i >> 4, c4 = (i & 15) * 4;
            float4 wv = *(const float4*)&Wsel[(size_t)(kc * 128 + r) * 128 + ch * 64 + c4];
            uint2 wh = { pack_bf16_hi(wv.x, wv.y), pack_bf16_hi(wv.z, wv.w) };
            uint2 wl = { pack_bf16_lo(wv.x, wv.y), pack_bf16_lo(wv.z, wv.w) };
            *(uint2*)(smem + OFF_BH + r * SBB_ + c4 * 2) = wh;
            *(uint2*)(smem + OFF_BL + r * SBB_ + c4 * 2) = wl;
        }
        __syncthreads();

#pragma unroll
        for (int k = 0; k < 8; k++) {
            uint32_t ah[4], al[4];
            ldsm4(ah, ahA + k * 32);
            ldsm4(al, alA + k * 32);
#pragma unroll
            for (int gp = 0; gp < 2; gp++) {
                const int a = 2 * gp, bq = 2 * gp + 1;
                uint32_t ba[4], bb[4];
                ldsm4t(ba, bhB + (uint32_t)(k * 16) * SBB_ + a * 32);
                ldsm4t(bb, bhB + (uint32_t)(k * 16) * SBB_ + bq * 32);
                mma16816(yv[2*a],    ah[0], ah[1], ah[2], ah[3], ba[0], ba[1]);
                mma16816(yv[2*a+1],  ah[0], ah[1], ah[2], ah[3], ba[2], ba[3]);
                mma16816(yv[2*bq],   ah[0], ah[1], ah[2], ah[3], bb[0], bb[1]);
                mma16816(yv[2*bq+1], ah[0], ah[1], ah[2], ah[3], bb[2], bb[3]);
                mma16816(yv[2*a],    al[0], al[1], al[2], al[3], ba[0], ba[1]);
                mma16816(yv[2*a+1],  al[0], al[1], al[2], al[3], ba[2], ba[3]);
                mma16816(yv[2*bq],   al[0], al[1], al[2], al[3], bb[0], bb[1]);
                mma16816(yv[2*bq+1], al[0], al[1], al[2], al[3], bb[2], bb[3]);
            }
#pragma unroll
            for (int gp = 0; gp < 2; gp++) {
                const int a = 2 * gp, bq = 2 * gp + 1;
                uint32_t ba[4], bb[4];
                ldsm4t(ba, blB + (uint32_t)(k * 16) * SBB_ + a * 32);
                ldsm4t(bb, blB + (uint32_t)(k * 16) * SBB_ + bq * 32);
                mma16816(yv[2*a],    ah[0], ah[1], ah[2], ah[3], ba[0], ba[1]);
                mma16816(yv[2*a+1],  ah[0], ah[1], ah[2], ah[3], ba[2], ba[3]);
                mma16816(yv[2*bq],   ah[0], ah[1], ah[2], ah[3], bb[0], bb[1]);
                mma16816(yv[2*bq+1], ah[0], ah[1], ah[2], ah[3], bb[2], bb[3]);
            }
        }
    }

    const int q  = lane >> 2;
    const int cb = 2 * (lane & 3);
    if (wi == 0) {
        const size_t rA = (size_t)(r0 + 16 * w + q) * 128 + ch * 64;
        const size_t rB = rA + 8 * 128;
#pragma unroll
        for (int nf = 0; nf < 8; nf++) {
            int c = nf * 8 + cb;
            *(uint32_t*)&d_th_hi[rA + c] = pack_bf16_hi(yv[nf][0], yv[nf][1]);
            *(uint32_t*)&d_th_lo[rA + c] = pack_bf16_lo(yv[nf][0], yv[nf][1]);
            *(uint32_t*)&d_th_hi[rB + c] = pack_bf16_hi(yv[nf][2], yv[nf][3]);
            *(uint32_t*)&d_th_lo[rB + c] = pack_bf16_lo(yv[nf][2], yv[nf][3]);
        }
    } else {
        __nv_bfloat16* dh = (wi == 1) ? d_ph_hi : d_g_hi;
        __nv_bfloat16* dl = (wi == 1) ? d_ph_lo : d_g_lo;
        float pm[8][4];
#pragma unroll
        for (int nf = 0; nf < 8; nf++)
#pragma unroll
            for (int j = 0; j < 4; j++)
                pm[nf][j] = fmaxf(yv[nf][j],
                                  __shfl_xor_sync(0xffffffffu, yv[nf][j], 4));
        if ((q & 1) == 0) {
            int rpA = (r0 + 16 * w + q) >> 1;
            int rpB = (r0 + 16 * w + 8 + q) >> 1;
            int bA = rpA / M_, mA = rpA - bA * M_;
            int bB = rpB / M_, mB = rpB - bB * M_;
            size_t dA = ((size_t)bA * MPAD_ + mA) * 128 + ch * 64;
            size_t dB = ((size_t)bB * MPAD_ + mB) * 128 + ch * 64;
#pragma unroll
            for (int nf = 0; nf < 8; nf++) {
                int c = nf * 8 + cb;
                *(uint32_t*)&dh[dA + c] = pack_bf16_hi(pm[nf][0], pm[nf][1]);
                *(uint32_t*)&dl[dA + c] = pack_bf16_lo(pm[nf][0], pm[nf][1]);
                *(uint32_t*)&dh[dB + c] = pack_bf16_hi(pm[nf][2], pm[nf][3]);
                *(uint32_t*)&dl[dB + c] = pack_bf16_lo(pm[nf][2], pm[nf][3]);
            }
        }
    }
}

// ===========================================================================
// K3: split-K flash attention (R13) with single-sync loop:
//     wait -> sync -> prefetch -> compute   (one barrier per iteration)
// ===========================================================================
__global__ __launch_bounds__(256, 1)
void k_attn15()
{
    extern __shared__ char smem[];
    const uint32_t sb = smem_u32(smem);
    const int b    = blockIdx.y;
    const int half = blockIdx.z;
    const int n0   = blockIdx.x * 128;
    const int t  = threadIdx.x;
    const int w  = t >> 5;
    const int lane = t & 31;
    const int tg  = lane >> 3;
    const int tr8 = lane & 7;

    const int aA_row  = ((tg & 1) << 3) + tr8;
    const int aA_colb = (tg & 2) * 8;
    const int bp_row  = ((tg & 2) << 2) + tr8;
    const int bp_colb = (tg & 1) * 16;

    const uint32_t phB_r = (uint32_t)bp_row * SB_ + bp_colb;
    const uint32_t ghB_r = (uint32_t)aA_row * SB_ + aA_colb;

    const int it0 = (half == 0) ? 0 : 9;
    const int nIt = (half == 0) ? 9 : 8;

    const int ld_r  = t >> 4;
    const int ld_c8 = (t & 15) * 8;

    uint32_t ath[8][4], atl[8][4];
    {
        int r0q = n0 + 16 * w + (lane >> 2);
        int rA = (r0q     < N_) ? r0q     : (N_ - 1);
        int rB = (r0q + 8 < N_) ? r0q + 8 : (N_ - 1);
        const __nv_bfloat16* th = d_th_hi + (size_t)b * N_ * 128;
        const __nv_bfloat16* tl = d_th_lo + (size_t)b * N_ * 128;
        const int cbf = (lane & 3) * 2;
#pragma unroll
        for (int k = 0; k < 8; k++) {
            int c = k * 16 + cbf;
            ath[k][0] = *(const uint32_t*)(th + (size_t)rA * 128 + c);
            ath[k][1] = *(const uint32_t*)(th + (size_t)rB * 128 + c);
            ath[k][2] = *(const uint32_t*)(th + (size_t)rA * 128 + c + 8);
            ath[k][3] = *(const uint32_t*)(th + (size_t)rB * 128 + c + 8);
            atl[k][0] = *(const uint32_t*)(tl + (size_t)rA * 128 + c);
            atl[k][1] = *(const uint32_t*)(tl + (size_t)rB * 128 + c);
            atl[k][2] = *(const uint32_t*)(tl + (size_t)rA * 128 + c + 8);
            atl[k][3] = *(const uint32_t*)(tl + (size_t)rB * 128 + c + 8);
        }
    }

    // prologue: chunk 0 -> buf0
    {
        const int m0 = it0 * KV;
#pragma unroll
        for (int q = 0; q < 6; q++) {
            int r = ld_r + 16 * q;
            size_t gidx = ((size_t)b * MPAD_ + m0 + r) * 128 + ld_c8;
            uint32_t so = sb + (uint32_t)r * SB_ + ld_c8 * 2;
            cp16(so + A_PHH, d_ph_hi + gidx);
            cp16(so + A_PHL, d_ph_lo + gidx);
            cp16(so + A_GH,  d_g_hi  + gidx);
            cp16(so + A_GL,  d_g_lo  + gidx);
        }
        asm volatile("cp.async.commit_group;");
    }

    float yv[16][4];
#pragma unroll
    for (int f = 0; f < 16; f++)
#pragma unroll
        for (int j = 0; j < 4; j++) yv[f][j] = 0.f;
    float mA = 0.f, mB = 0.f, lA = 0.f, lB = 0.f;

    for (int ii = 0; ii < nIt; ii++) {
        // wait own cp group for buf(ii&1), then single barrier
        asm volatile("cp.async.wait_group 0;");
        __syncthreads();
        // prefetch next chunk into the other buffer (safe: all warps are past
        // their reads of that buffer from iteration ii-1)
        if (ii + 1 < nIt) {
            const int m0n = (it0 + ii + 1) * KV;
            const uint32_t bufn = sb + (uint32_t)((ii + 1) & 1) * BUFA;
#pragma unroll
            for (int q = 0; q < 6; q++) {
                int r = ld_r + 16 * q;
                size_t gidx = ((size_t)b * MPAD_ + m0n + r) * 128 + ld_c8;
                uint32_t so = bufn + (uint32_t)r * SB_ + ld_c8 * 2;
                cp16(so + A_PHH, d_ph_hi + gidx);
                cp16(so + A_PHL, d_ph_lo + gidx);
                cp16(so + A_GH,  d_g_hi  + gidx);
                cp16(so + A_GL,  d_g_lo  + gidx);
            }
            asm volatile("cp.async.commit_group;");
        }

        const uint32_t bufc = sb + (uint32_t)(ii & 1) * BUFA;
        const uint32_t phB = bufc + A_PHH + phB_r;
        const uint32_t plB = bufc + A_PHL + phB_r;
        const uint32_t ghB = bufc + A_GH  + ghB_r;
        const uint32_t glB = bufc + A_GL  + ghB_r;

        float sf[12][4];
#pragma unroll
        for (int f = 0; f < 12; f++)
#pragma unroll
            for (int j = 0; j < 4; j++) sf[f][j] = 0.f;

#pragma unroll
        for (int k = 0; k < 8; k++) {
#pragma unroll
            for (int np = 0; np < 3; np++) {
                const int a = 2 * np, bq = 2 * np + 1;
                uint32_t ba[4], bb[4];
                ldsm4(ba, phB + (uint32_t)(a  * 16) * SB_ + k * 32);
                ldsm4(bb, phB + (uint32_t)(bq * 16) * SB_ + k * 32);
                mma16816(sf[2*a],    ath[k][0], ath[k][1], ath[k][2], ath[k][3], ba[0], ba[1]);
                mma16816(sf[2*a+1],  ath[k][0], ath[k][1], ath[k][2], ath[k][3], ba[2], ba[3]);
                mma16816(sf[2*bq],   ath[k][0], ath[k][1], ath[k][2], ath[k][3], bb[0], bb[1]);
                mma16816(sf[2*bq+1], ath[k][0], ath[k][1], ath[k][2], ath[k][3], bb[2], bb[3]);
                mma16816(sf[2*a],    atl[k][0], atl[k][1], atl[k][2], atl[k][3], ba[0], ba[1]);
                mma16816(sf[2*a+1],  atl[k][0], atl[k][1], atl[k][2], atl[k][3], ba[2], ba[3]);
                mma16816(sf[2*bq],   atl[k][0], atl[k][1], atl[k][2], atl[k][3], bb[0], bb[1]);
                mma16816(sf[2*bq+1], atl[k][0], atl[k][1], atl[k][2], atl[k][3], bb[2], bb[3]);
            }
#pragma unroll
            for (int np = 0; np < 3; np++) {
                const int a = 2 * np, bq = 2 * np + 1;
                uint32_t ba[4], bb[4];
                ldsm4(ba, plB + (uint32_t)(a  * 16) * SB_ + k * 32);
                ldsm4(bb, plB + (uint32_t)(bq * 16) * SB_ + k * 32);
                mma16816(sf[2*a],    ath[k][0], ath[k][1], ath[k][2], ath[k][3], ba[0], ba[1]);
                mma16816(sf[2*a+1],  ath[k][0], ath[k][1], ath[k][2], ath[k][3], ba[2], ba[3]);
                mma16816(sf[2*bq],   ath[k][0], ath[k][1], ath[k][2], ath[k][3], bb[0], bb[1]);
                mma16816(sf[2*bq+1], ath[k][0], ath[k][1], ath[k][2], ath[k][3], bb[2], bb[3]);
            }
        }

        if (ii == 0) {
            float mxA = -1e30f, mxB = -1e30f;
#pragma unroll
            for (int f = 0; f < 12; f++) {
                mxA = fmaxf(mxA, fmaxf(sf[f][0], sf[f][1]));
                mxB = fmaxf(mxB, fmaxf(sf[f][2], sf[f][3]));
            }
            mxA = fmaxf(mxA, __shfl_xor_sync(0xffffffffu, mxA, 1));
            mxA = fmaxf(mxA, __shfl_xor_sync(0xffffffffu, mxA, 2));
            mxB = fmaxf(mxB, __shfl_xor_sync(0xffffffffu, mxB, 1));
            mxB = fmaxf(mxB, __shfl_xor_sync(0xffffffffu, mxB, 2));
            mA = mxA; mB = mxB;
        }

#pragma unroll
        for (int ks = 0; ks < 6; ks++) {
            uint32_t pah[4], pal[4];
#pragma unroll
            for (int h = 0; h < 2; h++) {
                int f = 2 * ks + h;
                float p0 = __expf(sf[f][0] - mA);
                float p1 = __expf(sf[f][1] - mA);
                float p2 = __expf(sf[f][2] - mB);
                float p3 = __expf(sf[f][3] - mB);
                lA += p0 + p1; lB += p2 + p3;
                pah[0 + 2 * h] = pack_bf16_hi(p0, p1);
                pah[1 + 2 * h] = pack_bf16_hi(p2, p3);
                pal[0 + 2 * h] = pack_bf16_lo(p0, p1);
                pal[1 + 2 * h] = pack_bf16_lo(p2, p3);
            }
            const uint32_t gb = (uint32_t)(ks * 16) * SB_;
#pragma unroll
            for (int gp = 0; gp < 4; gp++) {
                const int a = 2 * gp, bq = 2 * gp + 1;
                uint32_t ba[4], bb[4];
                ldsm4t(ba, ghB + gb + a  * 32);
                ldsm4t(bb, ghB + gb + bq * 32);
                mma16816(yv[2*a],    pah[0], pah[1], pah[2], pah[3], ba[0], ba[1]);
                mma16816(yv[2*a+1],  pah[0], pah[1], pah[2], pah[3], ba[2], ba[3]);
                mma16816(yv[2*bq],   pah[0], pah[1], pah[2], pah[3], bb[0], bb[1]);
                mma16816(yv[2*bq+1], pah[0], pah[1], pah[2], pah[3], bb[2], bb[3]);
                mma16816(yv[2*a],    pal[0], pal[1], pal[2], pal[3], ba[0], ba[1]);
                mma16816(yv[2*a+1],  pal[0], pal[1], pal[2], pal[3], ba[2], ba[3]);
                mma16816(yv[2*bq],   pal[0], pal[1], pal[2], pal[3], bb[0], bb[1]);
                mma16816(yv[2*bq+1], pal[0], pal[1], pal[2], pal[3], bb[2], bb[3]);
            }
#pragma unroll
            for (int gp = 0; gp < 4; gp++) {
                const int a = 2 * gp, bq = 2 * gp + 1;
                uint32_t ba[4], bb[4];
                ldsm4t(ba, glB + gb + a  * 32);
                ldsm4t(bb, glB + gb + bq * 32);
                mma16816(yv[2*a],    pah[0], pah[1], pah[2], pah[3], ba[0], ba[1]);
                mma16816(yv[2*a+1],  pah[0], pah[1], pah[2], pah[3], ba[2], ba[3]);
                mma16816(yv[2*bq],   pah[0], pah[1], pah[2], pah[3], bb[0], bb[1]);
                mma16816(yv[2*bq+1], pah[0], pah[1], pah[2], pah[3], bb[2], bb[3]);
            }
        }
    }

    lA += __shfl_xor_sync(0xffffffffu, lA, 1);
    lA += __shfl_xor_sync(0xffffffffu, lA, 2);
    lB += __shfl_xor_sync(0xffffffffu, lB, 1);
    lB += __shfl_xor_sync(0xffffffffu, lB, 2);

    const int nA = n0 + 16 * w + (lane >> 2);
    const int nB = nA + 8;
    const int cb = 2 * (lane & 3);
    if (nA < N_) {
        size_t base = ((size_t)b * N_ + nA) * 128;
#pragma unroll
        for (int nf = 0; nf < 16; nf++) {
            float2 v = { yv[nf][0], yv[nf][1] };
            *(float2*)&d_py[half][base + nf * 8 + cb] = v;
        }
        if ((lane & 3) == 0) {
            d_pm[half][b * N_ + nA] = mA;
            d_pl[half][b * N_ + nA] = lA;
        }
    }
    if (nB < N_) {
        size_t base = ((size_t)b * N_ + nB) * 128;
#pragma unroll
        for (int nf = 0; nf < 16; nf++) {
            float2 v = { yv[nf][2], yv[nf][3] };
            *(float2*)&d_py[half][base + nf * 8 + cb] = v;
        }
        if ((lane & 3) == 0) {
            d_pm[half][b * N_ + nB] = mB;
            d_pl[half][b * N_ + nB] = lB;
        }
    }
}

// ===========================================================================
// K3b: combine split-K halves -> split-bf16 Y  (R13 version)
// ===========================================================================
__global__ __launch_bounds__(256)
void k_combine()
{
    int idx = blockIdx.x * 256 + threadIdx.x;
    if (idx >= ROWS_ * 32) return;
    int row = idx >> 5;
    int c4  = (idx & 31) * 4;
    float m0 = d_pm[0][row], m1 = d_pm[1][row];
    float l0 = d_pl[0][row], l1 = d_pl[1][row];
    float m  = fmaxf(m0, m1);
    float w0 = __expf(m0 - m), w1 = __expf(m1 - m);
    float inv = 1.f / (l0 * w0 + l1 * w1);
    w0 *= inv; w1 *= inv;
    size_t base = (size_t)row * 128 + c4;
    float4 y0 = *(const float4*)&d_py[0][base];
    float4 y1 = *(const float4*)&d_py[1][base];
    float v0 = y0.x * w0 + y1.x * w1;
    float v1 = y0.y * w0 + y1.y * w1;
    float v2 = y0.z * w0 + y1.z * w1;
    float v3 = y0.w * w0 + y1.w * w1;
    uint2 h = { pack_bf16_hi(v0, v1), pack_bf16_hi(v2, v3) };
    uint2 l = { pack_bf16_lo(v0, v1), pack_bf16_lo(v2, v3) };
    *(uint2*)&d_y_hi[base] = h;
    *(uint2*)&d_y_lo[base] = l;
}

// ===========================================================================
// K4: out = x + Y @ Wf (128-wide, R13 version)
// ===========================================================================
__global__ __launch_bounds__(256, 1)
void k_finalmma(const float* __restrict__ X,
                const float* __restrict__ Wf,
                float* __restrict__ out)
{
    extern __shared__ char smem[];
    const uint32_t sb = smem_u32(smem);
    const int r0 = blockIdx.x * 128;
    const int ch = blockIdx.y;
    const int t  = threadIdx.x;
    const int w  = t >> 5;
    const int lane = t & 31;
    const int tg  = lane >> 3;
    const int tr8 = lane & 7;
    const int aA_row  = ((tg & 1) << 3) + tr8;
    const int aA_colb = (tg & 2) * 8;

    const uint32_t ahA = sb + F_AH + (uint32_t)(16 * w + aA_row) * SB_ + aA_colb;
    const uint32_t alA = sb + F_AL + (uint32_t)(16 * w + aA_row) * SB_ + aA_colb;
    const uint32_t bhB = sb + F_BH + (uint32_t)aA_row * SB_ + aA_colb;
    const uint32_t blB = sb + F_BL + (uint32_t)aA_row * SB_ + aA_colb;

#pragma unroll
    for (int q = 0; q < 8; q++) {
        int i = t + 256 * q;
        int r = i >> 4, c8 = (i & 15) * 8;
        size_t gidx = (size_t)(r0 + r) * 128 + c8;
        *(uint4*)(smem + F_AH + r * SB_ + c8 * 2) = *(const uint4*)(d_y_hi + gidx);
        *(uint4*)(smem + F_AL + r * SB_ + c8 * 2) = *(const uint4*)(d_y_lo + gidx);
    }
#pragma unroll
    for (int q = 0; q < 16; q++) {
        int i = t + 256 * q;
        int r = i >> 5, c4 = (i & 31) * 4;
        float4 wv = *(const float4*)&Wf[(size_t)r * 256 + ch * 128 + c4];
        uint2 wh = { pack_bf16_hi(wv.x, wv.y), pack_bf16_hi(wv.z, wv.w) };
        uint2 wl = { pack_bf16_lo(wv.x, wv.y), pack_bf16_lo(wv.z, wv.w) };
        *(uint2*)(smem + F_BH + r * SB_ + c4 * 2) = wh;
        *(uint2*)(smem + F_BL + r * SB_ + c4 * 2) = wl;
    }
    __syncthreads();

    float yv[16][4];
#pragma unroll
    for (int f = 0; f < 16; f++)
#pragma unroll
        for (int j = 0; j < 4; j++) yv[f][j] = 0.f;

#pragma unroll
    for (int k = 0; k < 8; k++) {
        uint32_t ah[4], al[4];
        ldsm4(ah, ahA + k * 32);
        ldsm4(al, alA + k * 32);
#pragma unroll
        for (int gp = 0; gp < 4; gp++) {
            const int a = 2 * gp, bq = 2 * gp + 1;
            uint32_t ba[4], bb[4];
            ldsm4t(ba, bhB + (uint32_t)(k * 16) * SB_ + a  * 32);
            ldsm4t(bb, bhB + (uint32_t)(k * 16) * SB_ + bq * 32);
            mma16816(yv[2*a],    ah[0], ah[1], ah[2], ah[3], ba[0], ba[1]);
            mma16816(yv[2*a+1],  ah[0], ah[1], ah[2], ah[3], ba[2], ba[3]);
            mma16816(yv[2*bq],   ah[0], ah[1], ah[2], ah[3], bb[0], bb[1]);
            mma16816(yv[2*bq+1], ah[0], ah[1], ah[2], ah[3], bb[2], bb[3]);
            mma16816(yv[2*a],    al[0], al[1], al[2], al[3], ba[0], ba[1]);
            mma16816(yv[2*a+1],  al[0], al[1], al[2], al[3], ba[2], ba[3]);
            mma16816(yv[2*bq],   al[0], al[1], al[2], al[3], bb[0], bb[1]);
            mma16816(yv[2*bq+1], al[0], al[1], al[2], al[3], bb[2], bb[3]);
        }
#pragma unroll
        for (int gp = 0; gp < 4; gp++) {
            const int a = 2 * gp, bq = 2 * gp + 1;
            uint32_t ba[4], bb[4];
            ldsm4t(ba, blB + (uint32_t)(k * 16) * SB_ + a  * 32);
            ldsm4t(bb, blB + (uint32_t)(k * 16) * SB_ + bq * 32);
            mma16816(yv[2*a],    ah[0], ah[1], ah[2], ah[3], ba[0], ba[1]);
            mma16816(yv[2*a+1],  ah[0], ah[1], ah[2], ah[3], ba[2], ba[3]);
            mma16816(yv[2*bq],   ah[0], ah[1], ah[2], ah[3], bb[0], bb[1]);
            mma16816(yv[2*bq+1], ah[0], ah[1], ah[2], ah[3], bb[2], bb[3]);
        }
    }

    const int q  = lane >> 2;
    const int cb = 2 * (lane & 3);
    const size_t rA = (size_t)(r0 + 16 * w + q) * 256 + ch * 128;
    const size_t rB = rA + 8 * 256;
#pragma unroll
    for (int nf = 0; nf < 16; nf++) {
        int c = nf * 8 + cb;
        float2 xa = *(const float2*)&X[rA + c];
        float2 xb = *(const float2*)&X[rB + c];
        float2 oa = { xa.x + yv[nf][0], xa.y + yv[nf][1] };
        float2 ob = { xb.x + yv[nf][2], xb.y + yv[nf][3] };
        *(float2*)&out[rA + c] = oa;
        *(float2*)&out[rB + c] = ob;
    }
}

// ===========================================================================
extern "C" void kernel_launch(void* const* d_in, const int* in_sizes, int n_in,
                              void* d_out, int out_size)
{
    const float* x  = (const float*)d_in[0];
    const float* wt = (const float*)d_in[1];
    const float* wp = (const float*)d_in[2];
    const float* wg = (const float*)d_in[3];
    const float* wf = (const float*)d_in[4];
    float* out = (float*)d_out;

    cudaFuncSetAttribute(k_projmma,  cudaFuncAttributeMaxDynamicSharedMemorySize, SM_PROJ);
    cudaFuncSetAttribute(k_attn15,   cudaFuncAttributeMaxDynamicSharedMemorySize, SM_ATTN);
    cudaFuncSetAttribute(k_finalmma, cudaFuncAttributeMaxDynamicSharedMemorySize, SM_FIN);

    {
        dim3 grid(ROWS_ / 128, 3, 2);
        k_projmma<<<grid, 256, SM_PROJ>>>(x, wt, wp, wg);
    }
    {
        dim3 grid(25, B_, 2);
        k_attn15<<<grid, 256, SM_ATTN>>>();
    }
    {
        k_combine<<<(ROWS_ * 32 + 255) / 256, 256>>>();
    }
    {
        dim3 grid(ROWS_ / 128, 2);
        k_finalmma<<<grid, 256, SM_FIN>>>(x, wf, out);
    }
}

// round 16
// speedup vs baseline: 1.0592x; 1.0392x over previous
#include <cuda_runtime.h>
#include <cuda_bf16.h>
#include <cstdint>

// Problem constants
#define B_    8
#define C_    256
#define CI_   128
#define N_    3136
#define M_    1568
#define MPAD_ 1632            // 17*96
#define ROWS_ (B_*N_)         // 25088
#define KV    96

// ---------------- scratch (device globals; zero-initialized) --------------
__device__ __nv_bfloat16 d_th_hi[ROWS_*CI_];
__device__ __nv_bfloat16 d_th_lo[ROWS_*CI_];
__device__ __nv_bfloat16 d_ph_hi[B_*MPAD_*CI_];
__device__ __nv_bfloat16 d_ph_lo[B_*MPAD_*CI_];
__device__ __nv_bfloat16 d_g_hi [B_*MPAD_*CI_];
__device__ __nv_bfloat16 d_g_lo [B_*MPAD_*CI_];
__device__ __nv_bfloat16 d_y_hi [ROWS_*CI_];
__device__ __nv_bfloat16 d_y_lo [ROWS_*CI_];
// split-K attention partials
__device__ float d_py[2][ROWS_*CI_];
__device__ float d_pm[2][ROWS_];
__device__ float d_pl[2][ROWS_];

// ======================= helpers ==========================================
__device__ __forceinline__ uint32_t smem_u32(const void* p) {
    uint32_t a;
    asm("{ .reg .u64 t; cvta.to.shared.u64 t, %1; cvt.u32.u64 %0, t; }"
        : "=r"(a) : "l"(p));
    return a;
}
__device__ __forceinline__ void ldsm4(uint32_t r[4], uint32_t addr) {
    asm volatile("ldmatrix.sync.aligned.m8n8.x4.shared.b16 {%0,%1,%2,%3}, [%4];"
                 : "=r"(r[0]), "=r"(r[1]), "=r"(r[2]), "=r"(r[3]) : "r"(addr));
}
__device__ __forceinline__ void ldsm4t(uint32_t r[4], uint32_t addr) {
    asm volatile("ldmatrix.sync.aligned.m8n8.x4.trans.shared.b16 {%0,%1,%2,%3}, [%4];"
                 : "=r"(r[0]), "=r"(r[1]), "=r"(r[2]), "=r"(r[3]) : "r"(addr));
}
__device__ __forceinline__ void mma16816(float c[4],
                                         uint32_t a0, uint32_t a1, uint32_t a2, uint32_t a3,
                                         uint32_t b0, uint32_t b1) {
    asm volatile(
        "mma.sync.aligned.m16n8k16.row.col.f32.bf16.bf16.f32 "
        "{%0,%1,%2,%3}, {%4,%5,%6,%7}, {%8,%9}, {%0,%1,%2,%3};"
        : "+f"(c[0]), "+f"(c[1]), "+f"(c[2]), "+f"(c[3])
        : "r"(a0), "r"(a1), "r"(a2), "r"(a3), "r"(b0), "r"(b1));
}
__device__ __forceinline__ void cp16(uint32_t saddr, const void* gptr) {
    asm volatile("cp.async.cg.shared.global [%0], [%1], 16;"
                 :: "r"(saddr), "l"(gptr));
}
__device__ __forceinline__ uint32_t pack_bf16_hi(float x, float y) {
    __nv_bfloat16 hx = __float2bfloat16(x), hy = __float2bfloat16(y);
    return (uint32_t)__bfloat16_as_ushort(hx) |
           ((uint32_t)__bfloat16_as_ushort(hy) << 16);
}
__device__ __forceinline__ uint32_t pack_bf16_lo(float x, float y) {
    __nv_bfloat16 hx = __float2bfloat16(x), hy = __float2bfloat16(y);
    __nv_bfloat16 lx = __float2bfloat16(x - __bfloat162float(hx));
    __nv_bfloat16 ly = __float2bfloat16(y - __bfloat162float(hy));
    return (uint32_t)__bfloat16_as_ushort(lx) |
           ((uint32_t)__bfloat16_as_ushort(ly) << 16);
}

// SMEM strides
#define SB_      272
#define SBB_     144
// attention smem: 2 buffers of [ph_hi|ph_lo|g_hi|g_lo], each 96 rows
#define A_PHH    0
#define A_PHL    26112
#define A_GH     52224
#define A_GL     78336
#define BUFA     104448
#define SM_ATTN  (2*BUFA)                // 208896
// gemm (proj col-split) smem
#define OFF_AH   0
#define OFF_AL   34816
#define OFF_BH   69632
#define OFF_BL   (69632 + 18432)
#define SM_PROJ  (OFF_BL + 18432)        // 106496 -> 2 CTAs/SM
// final (128-wide) smem
#define F_AH     0
#define F_AL     34816
#define F_BH     69632
#define F_BL     104448
#define SM_FIN   139264

// ===========================================================================
// K1: projections, col-split 64-wide; mma pairs interleaved (R13)
// ===========================================================================
__global__ __launch_bounds__(256, 2)
void k_projmma(const float* __restrict__ X,
               const float* __restrict__ Wt,
               const float* __restrict__ Wp,
               const float* __restrict__ Wg)
{
    extern __shared__ char smem[];
    const uint32_t sb = smem_u32(smem);
    const int wi = blockIdx.y;
    const int ch = blockIdx.z;
    const float* Wsel = (wi == 0) ? Wt : ((wi == 1) ? Wp : Wg);
    const int r0 = blockIdx.x * 128;
    const int t  = threadIdx.x;
    const int w  = t >> 5;
    const int lane = t & 31;
    const int tg  = lane >> 3;
    const int tr8 = lane & 7;
    const int aA_row  = ((tg & 1) << 3) + tr8;
    const int aA_colb = (tg & 2) * 8;

    const uint32_t ahA = sb + OFF_AH + (uint32_t)(16 * w + aA_row) * SB_ + aA_colb;
    const uint32_t alA = sb + OFF_AL + (uint32_t)(16 * w + aA_row) * SB_ + aA_colb;
    const uint32_t bhB = sb + OFF_BH + (uint32_t)aA_row * SBB_ + aA_colb;
    const uint32_t blB = sb + OFF_BL + (uint32_t)aA_row * SBB_ + aA_colb;

    float yv[8][4];
#pragma unroll
    for (int f = 0; f < 8; f++)
#pragma unroll
        for (int j = 0; j < 4; j++) yv[f][j] = 0.f;

    for (int kc = 0; kc < 2; kc++) {
        if (kc) __syncthreads();
#pragma unroll
        for (int q = 0; q < 16; q++) {
            int i = t + 256 * q;
            int r = i >> 5, c4 = (i & 31) * 4;
            float4 v = *(const float4*)&X[(size_t)(r0 + r) * 256 + kc * 128 + c4];
            uint2 h = { pack_bf16_hi(v.x, v.y), pack_bf16_hi(v.z, v.w) };
            uint2 l = { pack_bf16_lo(v.x, v.y), pack_bf16_lo(v.z, v.w) };
            *(uint2*)(smem + OFF_AH + r * SB_ + c4 * 2) = h;
            *(uint2*)(smem + OFF_AL + r * SB_ + c4 * 2) = l;
        }
#pragma unroll
        for (int q = 0; q < 8; q++) {
            int i = t + 256 * q;
            int r = i >> 4, c4 = (i & 15) * 4;
            float4 wv = *(const float4*)&Wsel[(size_t)(kc * 128 + r) * 128 + ch * 64 + c4];
            uint2 wh = { pack_bf16_hi(wv.x, wv.y), pack_bf16_hi(wv.z, wv.w) };
            uint2 wl = { pack_bf16_lo(wv.x, wv.y), pack_bf16_lo(wv.z, wv.w) };
            *(uint2*)(smem + OFF_BH + r * SBB_ + c4 * 2) = wh;
            *(uint2*)(smem + OFF_BL + r * SBB_ + c4 * 2) = wl;
        }
        __syncthreads();

#pragma unroll
        for (int k = 0; k < 8; k++) {
            uint32_t ah[4], al[4];
            ldsm4(ah, ahA + k * 32);
            ldsm4(al, alA + k * 32);
#pragma unroll
            for (int gp = 0; gp < 2; gp++) {
                const int a = 2 * gp, bq = 2 * gp + 1;
                uint32_t ba[4], bb[4];
                ldsm4t(ba, bhB + (uint32_t)(k * 16) * SBB_ + a * 32);
                ldsm4t(bb, bhB + (uint32_t)(k * 16) * SBB_ + bq * 32);
                mma16816(yv[2*a],    ah[0], ah[1], ah[2], ah[3], ba[0], ba[1]);
                mma16816(yv[2*a+1],  ah[0], ah[1], ah[2], ah[3], ba[2], ba[3]);
                mma16816(yv[2*bq],   ah[0], ah[1], ah[2], ah[3], bb[0], bb[1]);
                mma16816(yv[2*bq+1], ah[0], ah[1], ah[2], ah[3], bb[2], bb[3]);
                mma16816(yv[2*a],    al[0], al[1], al[2], al[3], ba[0], ba[1]);
                mma16816(yv[2*a+1],  al[0], al[1], al[2], al[3], ba[2], ba[3]);
                mma16816(yv[2*bq],   al[0], al[1], al[2], al[3], bb[0], bb[1]);
                mma16816(yv[2*bq+1], al[0], al[1], al[2], al[3], bb[2], bb[3]);
            }
#pragma unroll
            for (int gp = 0; gp < 2; gp++) {
                const int a = 2 * gp, bq = 2 * gp + 1;
                uint32_t ba[4], bb[4];
                ldsm4t(ba, blB + (uint32_t)(k * 16) * SBB_ + a * 32);
                ldsm4t(bb, blB + (uint32_t)(k * 16) * SBB_ + bq * 32);
                mma16816(yv[2*a],    ah[0], ah[1], ah[2], ah[3], ba[0], ba[1]);
                mma16816(yv[2*a+1],  ah[0], ah[1], ah[2], ah[3], ba[2], ba[3]);
                mma16816(yv[2*bq],   ah[0], ah[1], ah[2], ah[3], bb[0], bb[1]);
                mma16816(yv[2*bq+1], ah[0], ah[1], ah[2], ah[3], bb[2], bb[3]);
            }
        }
    }

    const int q  = lane >> 2;
    const int cb = 2 * (lane & 3);
    if (wi == 0) {
        const size_t rA = (size_t)(r0 + 16 * w + q) * 128 + ch * 64;
        const size_t rB = rA + 8 * 128;
#pragma unroll
        for (int nf = 0; nf < 8; nf++) {
            int c = nf * 8 + cb;
            *(uint32_t*)&d_th_hi[rA + c] = pack_bf16_hi(yv[nf][0], yv[nf][1]);
            *(uint32_t*)&d_th_lo[rA + c] = pack_bf16_lo(yv[nf][0], yv[nf][1]);
            *(uint32_t*)&d_th_hi[rB + c] = pack_bf16_hi(yv[nf][2], yv[nf][3]);
            *(uint32_t*)&d_th_lo[rB + c] = pack_bf16_lo(yv[nf][2], yv[nf][3]);
        }
    } else {
        __nv_bfloat16* dh = (wi == 1) ? d_ph_hi : d_g_hi;
        __nv_bfloat16* dl = (wi == 1) ? d_ph_lo : d_g_lo;
        float pm[8][4];
#pragma unroll
        for (int nf = 0; nf < 8; nf++)
#pragma unroll
            for (int j = 0; j < 4; j++)
                pm[nf][j] = fmaxf(yv[nf][j],
                                  __shfl_xor_sync(0xffffffffu, yv[nf][j], 4));
        if ((q & 1) == 0) {
            int rpA = (r0 + 16 * w + q) >> 1;
            int rpB = (r0 + 16 * w + 8 + q) >> 1;
            int bA = rpA / M_, mA = rpA - bA * M_;
            int bB = rpB / M_, mB = rpB - bB * M_;
            size_t dA = ((size_t)bA * MPAD_ + mA) * 128 + ch * 64;
            size_t dB = ((size_t)bB * MPAD_ + mB) * 128 + ch * 64;
#pragma unroll
            for (int nf = 0; nf < 8; nf++) {
                int c = nf * 8 + cb;
                *(uint32_t*)&dh[dA + c] = pack_bf16_hi(pm[nf][0], pm[nf][1]);
                *(uint32_t*)&dl[dA + c] = pack_bf16_lo(pm[nf][0], pm[nf][1]);
                *(uint32_t*)&dh[dB + c] = pack_bf16_hi(pm[nf][2], pm[nf][3]);
                *(uint32_t*)&dl[dB + c] = pack_bf16_lo(pm[nf][2], pm[nf][3]);
            }
        }
    }
}

// ===========================================================================
// K3: split-K flash attention (R15 single-sync loop), UNEQUAL split 12/5:
//     big items (z=0, 12 iters) launch first to pack waves better.
// ===========================================================================
__global__ __launch_bounds__(256, 1)
void k_attn16()
{
    extern __shared__ char smem[];
    const uint32_t sb = smem_u32(smem);
    const int b    = blockIdx.y;
    const int half = blockIdx.z;
    const int n0   = blockIdx.x * 128;
    const int t  = threadIdx.x;
    const int w  = t >> 5;
    const int lane = t & 31;
    const int tg  = lane >> 3;
    const int tr8 = lane & 7;

    const int aA_row  = ((tg & 1) << 3) + tr8;
    const int aA_colb = (tg & 2) * 8;
    const int bp_row  = ((tg & 2) << 2) + tr8;
    const int bp_colb = (tg & 1) * 16;

    const uint32_t phB_r = (uint32_t)bp_row * SB_ + bp_colb;
    const uint32_t ghB_r = (uint32_t)aA_row * SB_ + aA_colb;

    // UNEQUAL split: big half = 12 iters (launches first), small half = 5
    const int it0 = (half == 0) ? 0 : 12;
    const int nIt = (half == 0) ? 12 : 5;

    const int ld_r  = t >> 4;
    const int ld_c8 = (t & 15) * 8;

    uint32_t ath[8][4], atl[8][4];
    {
        int r0q = n0 + 16 * w + (lane >> 2);
        int rA = (r0q     < N_) ? r0q     : (N_ - 1);
        int rB = (r0q + 8 < N_) ? r0q + 8 : (N_ - 1);
        const __nv_bfloat16* th = d_th_hi + (size_t)b * N_ * 128;
        const __nv_bfloat16* tl = d_th_lo + (size_t)b * N_ * 128;
        const int cbf = (lane & 3) * 2;
#pragma unroll
        for (int k = 0; k < 8; k++) {
            int c = k * 16 + cbf;
            ath[k][0] = *(const uint32_t*)(th + (size_t)rA * 128 + c);
            ath[k][1] = *(const uint32_t*)(th + (size_t)rB * 128 + c);
            ath[k][2] = *(const uint32_t*)(th + (size_t)rA * 128 + c + 8);
            ath[k][3] = *(const uint32_t*)(th + (size_t)rB * 128 + c + 8);
            atl[k][0] = *(const uint32_t*)(tl + (size_t)rA * 128 + c);
            atl[k][1] = *(const uint32_t*)(tl + (size_t)rB * 128 + c);
            atl[k][2] = *(const uint32_t*)(tl + (size_t)rA * 128 + c + 8);
            atl[k][3] = *(const uint32_t*)(tl + (size_t)rB * 128 + c + 8);
        }
    }

    // prologue: first chunk -> buf0
    {
        const int m0 = it0 * KV;
#pragma unroll
        for (int q = 0; q < 6; q++) {
            int r = ld_r + 16 * q;
            size_t gidx = ((size_t)b * MPAD_ + m0 + r) * 128 + ld_c8;
            uint32_t so = sb + (uint32_t)r * SB_ + ld_c8 * 2;
            cp16(so + A_PHH, d_ph_hi + gidx);
            cp16(so + A_PHL, d_ph_lo + gidx);
            cp16(so + A_GH,  d_g_hi  + gidx);
            cp16(so + A_GL,  d_g_lo  + gidx);
        }
        asm volatile("cp.async.commit_group;");
    }

    float yv[16][4];
#pragma unroll
    for (int f = 0; f < 16; f++)
#pragma unroll
        for (int j = 0; j < 4; j++) yv[f][j] = 0.f;
    float mA = 0.f, mB = 0.f, lA = 0.f, lB = 0.f;

    for (int ii = 0; ii < nIt; ii++) {
        asm volatile("cp.async.wait_group 0;");
        __syncthreads();
        if (ii + 1 < nIt) {
            const int m0n = (it0 + ii + 1) * KV;
            const uint32_t bufn = sb + (uint32_t)((ii + 1) & 1) * BUFA;
#pragma unroll
            for (int q = 0; q < 6; q++) {
                int r = ld_r + 16 * q;
                size_t gidx = ((size_t)b * MPAD_ + m0n + r) * 128 + ld_c8;
                uint32_t so = bufn + (uint32_t)r * SB_ + ld_c8 * 2;
                cp16(so + A_PHH, d_ph_hi + gidx);
                cp16(so + A_PHL, d_ph_lo + gidx);
                cp16(so + A_GH,  d_g_hi  + gidx);
                cp16(so + A_GL,  d_g_lo  + gidx);
            }
            asm volatile("cp.async.commit_group;");
        }

        const uint32_t bufc = sb + (uint32_t)(ii & 1) * BUFA;
        const uint32_t phB = bufc + A_PHH + phB_r;
        const uint32_t plB = bufc + A_PHL + phB_r;
        const uint32_t ghB = bufc + A_GH  + ghB_r;
        const uint32_t glB = bufc + A_GL  + ghB_r;

        float sf[12][4];
#pragma unroll
        for (int f = 0; f < 12; f++)
#pragma unroll
            for (int j = 0; j < 4; j++) sf[f][j] = 0.f;

#pragma unroll
        for (int k = 0; k < 8; k++) {
#pragma unroll
            for (int np = 0; np < 3; np++) {
                const int a = 2 * np, bq = 2 * np + 1;
                uint32_t ba[4], bb[4];
                ldsm4(ba, phB + (uint32_t)(a  * 16) * SB_ + k * 32);
                ldsm4(bb, phB + (uint32_t)(bq * 16) * SB_ + k * 32);
                mma16816(sf[2*a],    ath[k][0], ath[k][1], ath[k][2], ath[k][3], ba[0], ba[1]);
                mma16816(sf[2*a+1],  ath[k][0], ath[k][1], ath[k][2], ath[k][3], ba[2], ba[3]);
                mma16816(sf[2*bq],   ath[k][0], ath[k][1], ath[k][2], ath[k][3], bb[0], bb[1]);
                mma16816(sf[2*bq+1], ath[k][0], ath[k][1], ath[k][2], ath[k][3], bb[2], bb[3]);
                mma16816(sf[2*a],    atl[k][0], atl[k][1], atl[k][2], atl[k][3], ba[0], ba[1]);
                mma16816(sf[2*a+1],  atl[k][0], atl[k][1], atl[k][2], atl[k][3], ba[2], ba[3]);
                mma16816(sf[2*bq],   atl[k][0], atl[k][1], atl[k][2], atl[k][3], bb[0], bb[1]);
                mma16816(sf[2*bq+1], atl[k][0], atl[k][1], atl[k][2], atl[k][3], bb[2], bb[3]);
            }
#pragma unroll
            for (int np = 0; np < 3; np++) {
                const int a = 2 * np, bq = 2 * np + 1;
                uint32_t ba[4], bb[4];
                ldsm4(ba, plB + (uint32_t)(a  * 16) * SB_ + k * 32);
                ldsm4(bb, plB + (uint32_t)(bq * 16) * SB_ + k * 32);
                mma16816(sf[2*a],    ath[k][0], ath[k][1], ath[k][2], ath[k][3], ba[0], ba[1]);
                mma16816(sf[2*a+1],  ath[k][0], ath[k][1], ath[k][2], ath[k][3], ba[2], ba[3]);
                mma16816(sf[2*bq],   ath[k][0], ath[k][1], ath[k][2], ath[k][3], bb[0], bb[1]);
                mma16816(sf[2*bq+1], ath[k][0], ath[k][1], ath[k][2], ath[k][3], bb[2], bb[3]);
            }
        }

        if (ii == 0) {
            float mxA = -1e30f, mxB = -1e30f;
#pragma unroll
            for (int f = 0; f < 12; f++) {
                mxA = fmaxf(mxA, fmaxf(sf[f][0], sf[f][1]));
                mxB = fmaxf(mxB, fmaxf(sf[f][2], sf[f][3]));
            }
            mxA = fmaxf(mxA, __shfl_xor_sync(0xffffffffu, mxA, 1));
            mxA = fmaxf(mxA, __shfl_xor_sync(0xffffffffu, mxA, 2));
            mxB = fmaxf(mxB, __shfl_xor_sync(0xffffffffu, mxB, 1));
            mxB = fmaxf(mxB, __shfl_xor_sync(0xffffffffu, mxB, 2));
            mA = mxA; mB = mxB;
        }

#pragma unroll
        for (int ks = 0; ks < 6; ks++) {
            uint32_t pah[4], pal[4];
#pragma unroll
            for (int h = 0; h < 2; h++) {
                int f = 2 * ks + h;
                float p0 = __expf(sf[f][0] - mA);
                float p1 = __expf(sf[f][1] - mA);
                float p2 = __expf(sf[f][2] - mB);
                float p3 = __expf(sf[f][3] - mB);
                lA += p0 + p1; lB += p2 + p3;
                pah[0 + 2 * h] = pack_bf16_hi(p0, p1);
                pah[1 + 2 * h] = pack_bf16_hi(p2, p3);
                pal[0 + 2 * h] = pack_bf16_lo(p0, p1);
                pal[1 + 2 * h] = pack_bf16_lo(p2, p3);
            }
            const uint32_t gb = (uint32_t)(ks * 16) * SB_;
#pragma unroll
            for (int gp = 0; gp < 4; gp++) {
                const int a = 2 * gp, bq = 2 * gp + 1;
                uint32_t ba[4], bb[4];
                ldsm4t(ba, ghB + gb + a  * 32);
                ldsm4t(bb, ghB + gb + bq * 32);
                mma16816(yv[2*a],    pah[0], pah[1], pah[2], pah[3], ba[0], ba[1]);
                mma16816(yv[2*a+1],  pah[0], pah[1], pah[2], pah[3], ba[2], ba[3]);
                mma16816(yv[2*bq],   pah[0], pah[1], pah[2], pah[3], bb[0], bb[1]);
                mma16816(yv[2*bq+1], pah[0], pah[1], pah[2], pah[3], bb[2], bb[3]);
                mma16816(yv[2*a],    pal[0], pal[1], pal[2], pal[3], ba[0], ba[1]);
                mma16816(yv[2*a+1],  pal[0], pal[1], pal[2], pal[3], ba[2], ba[3]);
                mma16816(yv[2*bq],   pal[0], pal[1], pal[2], pal[3], bb[0], bb[1]);
                mma16816(yv[2*bq+1], pal[0], pal[1], pal[2], pal[3], bb[2], bb[3]);
            }
#pragma unroll
            for (int gp = 0; gp < 4; gp++) {
                const int a = 2 * gp, bq = 2 * gp + 1;
                uint32_t ba[4], bb[4];
                ldsm4t(ba, glB + gb + a  * 32);
                ldsm4t(bb, glB + gb + bq * 32);
                mma16816(yv[2*a],    pah[0], pah[1], pah[2], pah[3], ba[0], ba[1]);
                mma16816(yv[2*a+1],  pah[0], pah[1], pah[2], pah[3], ba[2], ba[3]);
                mma16816(yv[2*bq],   pah[0], pah[1], pah[2], pah[3], bb[0], bb[1]);
                mma16816(yv[2*bq+1], pah[0], pah[1], pah[2], pah[3], bb[2], bb[3]);
            }
        }
    }

    lA += __shfl_xor_sync(0xffffffffu, lA, 1);
    lA += __shfl_xor_sync(0xffffffffu, lA, 2);
    lB += __shfl_xor_sync(0xffffffffu, lB, 1);
    lB += __shfl_xor_sync(0xffffffffu, lB, 2);

    const int nA = n0 + 16 * w + (lane >> 2);
    const int nB = nA + 8;
    const int cb = 2 * (lane & 3);
    if (nA < N_) {
        size_t base = ((size_t)b * N_ + nA) * 128;
#pragma unroll
        for (int nf = 0; nf < 16; nf++) {
            float2 v = { yv[nf][0], yv[nf][1] };
            *(float2*)&d_py[half][base + nf * 8 + cb] = v;
        }
        if ((lane & 3) == 0) {
            d_pm[half][b * N_ + nA] = mA;
            d_pl[half][b * N_ + nA] = lA;
        }
    }
    if (nB < N_) {
        size_t base = ((size_t)b * N_ + nB) * 128;
#pragma unroll
        for (int nf = 0; nf < 16; nf++) {
            float2 v = { yv[nf][2], yv[nf][3] };
            *(float2*)&d_py[half][base + nf * 8 + cb] = v;
        }
        if ((lane & 3) == 0) {
            d_pm[half][b * N_ + nB] = mB;
            d_pl[half][b * N_ + nB] = lB;
        }
    }
}

// ===========================================================================
// K3b: combine split-K halves -> split-bf16 Y
// ===========================================================================
__global__ __launch_bounds__(256)
void k_combine()
{
    int idx = blockIdx.x * 256 + threadIdx.x;
    if (idx >= ROWS_ * 32) return;
    int row = idx >> 5;
    int c4  = (idx & 31) * 4;
    float m0 = d_pm[0][row], m1 = d_pm[1][row];
    float l0 = d_pl[0][row], l1 = d_pl[1][row];
    float m  = fmaxf(m0, m1);
    float w0 = __expf(m0 - m), w1 = __expf(m1 - m);
    float inv = 1.f / (l0 * w0 + l1 * w1);
    w0 *= inv; w1 *= inv;
    size_t base = (size_t)row * 128 + c4;
    float4 y0 = *(const float4*)&d_py[0][base];
    float4 y1 = *(const float4*)&d_py[1][base];
    float v0 = y0.x * w0 + y1.x * w1;
    float v1 = y0.y * w0 + y1.y * w1;
    float v2 = y0.z * w0 + y1.z * w1;
    float v3 = y0.w * w0 + y1.w * w1;
    uint2 h = { pack_bf16_hi(v0, v1), pack_bf16_hi(v2, v3) };
    uint2 l = { pack_bf16_lo(v0, v1), pack_bf16_lo(v2, v3) };
    *(uint2*)&d_y_hi[base] = h;
    *(uint2*)&d_y_lo[base] = l;
}

// ===========================================================================
// K4: out = x + Y @ Wf (128-wide, R13 version)
// ===========================================================================
__global__ __launch_bounds__(256, 1)
void k_finalmma(const float* __restrict__ X,
                const float* __restrict__ Wf,
                float* __restrict__ out)
{
    extern __shared__ char smem[];
    const uint32_t sb = smem_u32(smem);
    const int r0 = blockIdx.x * 128;
    const int ch = blockIdx.y;
    const int t  = threadIdx.x;
    const int w  = t >> 5;
    const int lane = t & 31;
    const int tg  = lane >> 3;
    const int tr8 = lane & 7;
    const int aA_row  = ((tg & 1) << 3) + tr8;
    const int aA_colb = (tg & 2) * 8;

    const uint32_t ahA = sb + F_AH + (uint32_t)(16 * w + aA_row) * SB_ + aA_colb;
    const uint32_t alA = sb + F_AL + (uint32_t)(16 * w + aA_row) * SB_ + aA_colb;
    const uint32_t bhB = sb + F_BH + (uint32_t)aA_row * SB_ + aA_colb;
    const uint32_t blB = sb + F_BL + (uint32_t)aA_row * SB_ + aA_colb;

#pragma unroll
    for (int q = 0; q < 8; q++) {
        int i = t + 256 * q;
        int r = i >> 4, c8 = (i & 15) * 8;
        size_t gidx = (size_t)(r0 + r) * 128 + c8;
        *(uint4*)(smem + F_AH + r * SB_ + c8 * 2) = *(const uint4*)(d_y_hi + gidx);
        *(uint4*)(smem + F_AL + r * SB_ + c8 * 2) = *(const uint4*)(d_y_lo + gidx);
    }
#pragma unroll
    for (int q = 0; q < 16; q++) {
        int i = t + 256 * q;
        int r = i >> 5, c4 = (i & 31) * 4;
        float4 wv = *(const float4*)&Wf[(size_t)r * 256 + ch * 128 + c4];
        uint2 wh = { pack_bf16_hi(wv.x, wv.y), pack_bf16_hi(wv.z, wv.w) };
        uint2 wl = { pack_bf16_lo(wv.x, wv.y), pack_bf16_lo(wv.z, wv.w) };
        *(uint2*)(smem + F_BH + r * SB_ + c4 * 2) = wh;
        *(uint2*)(smem + F_BL + r * SB_ + c4 * 2) = wl;
    }
    __syncthreads();

    float yv[16][4];
#pragma unroll
    for (int f = 0; f < 16; f++)
#pragma unroll
        for (int j = 0; j < 4; j++) yv[f][j] = 0.f;

#pragma unroll
    for (int k = 0; k < 8; k++) {
        uint32_t ah[4], al[4];
        ldsm4(ah, ahA + k * 32);
        ldsm4(al, alA + k * 32);
#pragma unroll
        for (int gp = 0; gp < 4; gp++) {
            const int a = 2 * gp, bq = 2 * gp + 1;
            uint32_t ba[4], bb[4];
            ldsm4t(ba, bhB + (uint32_t)(k * 16) * SB_ + a  * 32);
            ldsm4t(bb, bhB + (uint32_t)(k * 16) * SB_ + bq * 32);
            mma16816(yv[2*a],    ah[0], ah[1], ah[2], ah[3], ba[0], ba[1]);
            mma16816(yv[2*a+1],  ah[0], ah[1], ah[2], ah[3], ba[2], ba[3]);
            mma16816(yv[2*bq],   ah[0], ah[1], ah[2], ah[3], bb[0], bb[1]);
            mma16816(yv[2*bq+1], ah[0], ah[1], ah[2], ah[3], bb[2], bb[3]);
            mma16816(yv[2*a],    al[0], al[1], al[2], al[3], ba[0], ba[1]);
            mma16816(yv[2*a+1],  al[0], al[1], al[2], al[3], ba[2], ba[3]);
            mma16816(yv[2*bq],   al[0], al[1], al[2], al[3], bb[0], bb[1]);
            mma16816(yv[2*bq+1], al[0], al[1], al[2], al[3], bb[2], bb[3]);
        }
#pragma unroll
        for (int gp = 0; gp < 4; gp++) {
            const int a = 2 * gp, bq = 2 * gp + 1;
            uint32_t ba[4], bb[4];
            ldsm4t(ba, blB + (uint32_t)(k * 16) * SB_ + a  * 32);
            ldsm4t(bb, blB + (uint32_t)(k * 16) * SB_ + bq * 32);
            mma16816(yv[2*a],    ah[0], ah[1], ah[2], ah[3], ba[0], ba[1]);
            mma16816(yv[2*a+1],  ah[0], ah[1], ah[2], ah[3], ba[2], ba[3]);
            mma16816(yv[2*bq],   ah[0], ah[1], ah[2], ah[3], bb[0], bb[1]);
            mma16816(yv[2*bq+1], ah[0], ah[1], ah[2], ah[3], bb[2], bb[3]);
        }
    }

    const int q  = lane >> 2;
    const int cb = 2 * (lane & 3);
    const size_t rA = (size_t)(r0 + 16 * w + q) * 256 + ch * 128;
    const size_t rB = rA + 8 * 256;
#pragma unroll
    for (int nf = 0; nf < 16; nf++) {
        int c = nf * 8 + cb;
        float2 xa = *(const float2*)&X[rA + c];
        float2 xb = *(const float2*)&X[rB + c];
        float2 oa = { xa.x + yv[nf][0], xa.y + yv[nf][1] };
        float2 ob = { xb.x + yv[nf][2], xb.y + yv[nf][3] };
        *(float2*)&out[rA + c] = oa;
        *(float2*)&out[rB + c] = ob;
    }
}

// ===========================================================================
extern "C" void kernel_launch(void* const* d_in, const int* in_sizes, int n_in,
                              void* d_out, int out_size)
{
    const float* x  = (const float*)d_in[0];
    const float* wt = (const float*)d_in[1];
    const float* wp = (const float*)d_in[2];
    const float* wg = (const float*)d_in[3];
    const float* wf = (const float*)d_in[4];
    float* out = (float*)d_out;

    cudaFuncSetAttribute(k_projmma,  cudaFuncAttributeMaxDynamicSharedMemorySize, SM_PROJ);
    cudaFuncSetAttribute(k_attn16,   cudaFuncAttributeMaxDynamicSharedMemorySize, SM_ATTN);
    cudaFuncSetAttribute(k_finalmma, cudaFuncAttributeMaxDynamicSharedMemorySize, SM_FIN);

    {
        dim3 grid(ROWS_ / 128, 3, 2);
        k_projmma<<<grid, 256, SM_PROJ>>>(x, wt, wp, wg);
    }
    {
        dim3 grid(25, B_, 2);
        k_attn16<<<grid, 256, SM_ATTN>>>();
    }
    {
        k_combine<<<(ROWS_ * 32 + 255) / 256, 256>>>();
    }
    {
        dim3 grid(ROWS_ / 128, 2);
        k_finalmma<<<grid, 256, SM_FIN>>>(x, wf, out);
    }
}